// round 1
// baseline (speedup 1.0000x reference)
#include <cuda_runtime.h>

// Problem constants
#define Eq 1024
#define NH 16
#define DH 64
#define NB 4
#define SL 2048   // SQ == SKV == 2048

// Scratch (alloc-free rule: __device__ globals)
__device__ float g_q[NB * NH * SL * DH];    // [B,H,SQ,HD]
__device__ float g_k[NB * NH * SL * DH];    // [B,H,SKV,HD]
__device__ float g_v[NB * NH * SL * DH];    // [B,H,SKV,HD]
__device__ float g_ctx[NB * SL * Eq];       // [B,SQ,E] flat

// ---------------------------------------------------------------------------
// GEMM: out = A @ W^T + bias.  A: [M=8192, K=1024] row-major, W: [N=1024, K=1024]
// MODE 0: write head-transposed layout [B,H,S,HD]; MODE 1: flat [M,N].
// 128x128x8 tile, 256 threads, 8x8 per-thread microtile.
// ---------------------------------------------------------------------------
template <int MODE>
__global__ __launch_bounds__(256) void gemm_kernel(
    const float* __restrict__ A, const float* __restrict__ W,
    const float* __restrict__ bias, float* __restrict__ out)
{
    __shared__ float As[8][128];
    __shared__ float Bs[8][128];
    const int K = Eq;
    const int m0 = blockIdx.y * 128;
    const int n0 = blockIdx.x * 128;
    const int tid = threadIdx.x;
    const int ty = tid >> 4;        // 0..15
    const int tx = tid & 15;        // 0..15
    const int lrow = tid >> 1;      // 0..127
    const int lk4 = (tid & 1) * 4;  // 0 or 4

    const float* Ap = A + (size_t)(m0 + lrow) * K + lk4;
    const float* Wp = W + (size_t)(n0 + lrow) * K + lk4;

    float acc[8][8];
#pragma unroll
    for (int i = 0; i < 8; i++)
#pragma unroll
        for (int j = 0; j < 8; j++) acc[i][j] = 0.0f;

    for (int k0 = 0; k0 < K; k0 += 8) {
        float4 a4 = *reinterpret_cast<const float4*>(Ap + k0);
        float4 w4 = *reinterpret_cast<const float4*>(Wp + k0);
        __syncthreads();
        As[lk4 + 0][lrow] = a4.x; As[lk4 + 1][lrow] = a4.y;
        As[lk4 + 2][lrow] = a4.z; As[lk4 + 3][lrow] = a4.w;
        Bs[lk4 + 0][lrow] = w4.x; Bs[lk4 + 1][lrow] = w4.y;
        Bs[lk4 + 2][lrow] = w4.z; Bs[lk4 + 3][lrow] = w4.w;
        __syncthreads();
#pragma unroll
        for (int kk = 0; kk < 8; kk++) {
            float a[8], b[8];
            *(float4*)&a[0] = *(const float4*)&As[kk][ty * 8];
            *(float4*)&a[4] = *(const float4*)&As[kk][ty * 8 + 4];
            *(float4*)&b[0] = *(const float4*)&Bs[kk][tx * 8];
            *(float4*)&b[4] = *(const float4*)&Bs[kk][tx * 8 + 4];
#pragma unroll
            for (int i = 0; i < 8; i++)
#pragma unroll
                for (int j = 0; j < 8; j++)
                    acc[i][j] = fmaf(a[i], b[j], acc[i][j]);
        }
    }

#pragma unroll
    for (int i = 0; i < 8; i++) {
        const int gm = m0 + ty * 8 + i;
#pragma unroll
        for (int j = 0; j < 8; j++) {
            const int gn = n0 + tx * 8 + j;
            const float val = acc[i][j] + bias[gn];
            if (MODE == 0) {
                const int bb = gm >> 11, ss = gm & 2047;
                const int hh = gn >> 6,  dd = gn & 63;
                out[(((size_t)(bb * NH + hh)) * SL + ss) * DH + dd] = val;
            } else {
                out[(size_t)gm * Eq + gn] = val;
            }
        }
    }
}

// ---------------------------------------------------------------------------
// Fused stablemax attention.
// Per block: 128 query rows of one (b,h). Stream 64-key tiles:
//   S = Q K^T / 8 ; T = stablemax-numerator(S) ; denom += rowsum(T) ; acc += T V
// Final: ctx[b, s, h*64+d] = acc / denom.
// ---------------------------------------------------------------------------
#define QP 132  // pitch for 128-wide transposed tiles (16B-aligned rows)
#define KP 68   // pitch for 64-wide tiles

#define ATTN_SMEM_FLOATS (64 * QP * 2 + 64 * KP * 2 + 128)
#define ATTN_SMEM_BYTES (ATTN_SMEM_FLOATS * 4)

__global__ __launch_bounds__(256) void attn_kernel(
    const float* __restrict__ q, const float* __restrict__ k,
    const float* __restrict__ v, float* __restrict__ ctx)
{
    extern __shared__ float sm[];
    float* qsT  = sm;                  // [d=64][m=128] pitch QP
    float* tsT  = qsT + 64 * QP;       // [n=64][m=128] pitch QP
    float* ksT  = tsT + 64 * QP;       // [d=64][n=64]  pitch KP
    float* vs   = ksT + 64 * KP;       // [n=64][d=64]  pitch KP
    float* dsum = vs + 64 * KP;        // [128]

    const int bh = blockIdx.y;          // b*NH + h
    const int q0 = blockIdx.x * 128;
    const int tid = threadIdx.x;
    const int ty = tid >> 4;            // row group 0..15 (8 rows each)
    const int tx = tid & 15;            // col group 0..15 (4 cols each)

    const float* qb = q + ((size_t)bh * SL + q0) * DH;
    const float* kb = k + (size_t)bh * SL * DH;
    const float* vb = v + (size_t)bh * SL * DH;

    // Load Q tile transposed: qsT[d][m]
    for (int it = tid; it < 128 * 16; it += 256) {
        const int row = it >> 4;
        const int c4 = (it & 15) * 4;
        float4 t4 = *(const float4*)(qb + row * DH + c4);
        qsT[(c4 + 0) * QP + row] = t4.x;
        qsT[(c4 + 1) * QP + row] = t4.y;
        qsT[(c4 + 2) * QP + row] = t4.z;
        qsT[(c4 + 3) * QP + row] = t4.w;
    }
    if (tid < 128) dsum[tid] = 0.0f;

    float oacc[8][4];
#pragma unroll
    for (int i = 0; i < 8; i++)
#pragma unroll
        for (int j = 0; j < 4; j++) oacc[i][j] = 0.0f;

    for (int kv0 = 0; kv0 < SL; kv0 += 64) {
        __syncthreads();  // protect ksT/vs/tsT from previous tile's readers
        // Load K tile transposed (ksT[d][n]) and V tile as-is (vs[n][d])
        for (int it = tid; it < 64 * 16; it += 256) {
            const int row = it >> 4;
            const int c4 = (it & 15) * 4;
            float4 k4 = *(const float4*)(kb + (size_t)(kv0 + row) * DH + c4);
            ksT[(c4 + 0) * KP + row] = k4.x;
            ksT[(c4 + 1) * KP + row] = k4.y;
            ksT[(c4 + 2) * KP + row] = k4.z;
            ksT[(c4 + 3) * KP + row] = k4.w;
            float4 v4 = *(const float4*)(vb + (size_t)(kv0 + row) * DH + c4);
            *(float4*)&vs[row * KP + c4] = v4;
        }
        __syncthreads();

        // GEMM1: S[m][n] = sum_d Q[m][d] K[n][d]
        float sacc[8][4];
#pragma unroll
        for (int i = 0; i < 8; i++)
#pragma unroll
            for (int j = 0; j < 4; j++) sacc[i][j] = 0.0f;

#pragma unroll 4
        for (int d = 0; d < 64; d++) {
            float qa[8], kv4[4];
            *(float4*)&qa[0] = *(const float4*)&qsT[d * QP + ty * 8];
            *(float4*)&qa[4] = *(const float4*)&qsT[d * QP + ty * 8 + 4];
            *(float4*)&kv4[0] = *(const float4*)&ksT[d * KP + tx * 4];
#pragma unroll
            for (int i = 0; i < 8; i++)
#pragma unroll
                for (int j = 0; j < 4; j++)
                    sacc[i][j] = fmaf(qa[i], kv4[j], sacc[i][j]);
        }

        // Transform (stablemax numerator) + per-row partial sums + write tsT[n][m]
        float rsum[8];
#pragma unroll
        for (int i = 0; i < 8; i++) rsum[i] = 0.0f;
#pragma unroll
        for (int i = 0; i < 8; i++) {
#pragma unroll
            for (int j = 0; j < 4; j++) {
                const float s = sacc[i][j] * 0.125f;  // 1/sqrt(64)
                const float t = (s >= 0.0f) ? (s + 1.0f) : (1.0f / (1.0f - s));
                tsT[(tx * 4 + j) * QP + ty * 8 + i] = t;
                rsum[i] += t;
            }
        }
        // Reduce rsum across the 16 lanes sharing this row group (xor<16 stays in group)
#pragma unroll
        for (int off = 1; off < 16; off <<= 1)
#pragma unroll
            for (int i = 0; i < 8; i++)
                rsum[i] += __shfl_xor_sync(0xffffffffu, rsum[i], off);
        if (tx == 0) {
#pragma unroll
            for (int i = 0; i < 8; i++) dsum[ty * 8 + i] += rsum[i];
        }
        __syncthreads();

        // GEMM2: acc[m][dv] += sum_n T[m][n] V[n][dv]
#pragma unroll 4
        for (int n = 0; n < 64; n++) {
            float tv[8], vv[4];
            *(float4*)&tv[0] = *(const float4*)&tsT[n * QP + ty * 8];
            *(float4*)&tv[4] = *(const float4*)&tsT[n * QP + ty * 8 + 4];
            *(float4*)&vv[0] = *(const float4*)&vs[n * KP + tx * 4];
#pragma unroll
            for (int i = 0; i < 8; i++)
#pragma unroll
                for (int j = 0; j < 4; j++)
                    oacc[i][j] = fmaf(tv[i], vv[j], oacc[i][j]);
        }
    }
    __syncthreads();  // dsum complete

    const int b = bh >> 4, h = bh & 15;
#pragma unroll
    for (int i = 0; i < 8; i++) {
        const int m = ty * 8 + i;
        const float inv = 1.0f / dsum[m];
        const size_t base = ((size_t)b * SL + q0 + m) * Eq + h * DH + tx * 4;
#pragma unroll
        for (int j = 0; j < 4; j++)
            ctx[base + j] = oacc[i][j] * inv;
    }
}

// ---------------------------------------------------------------------------
extern "C" void kernel_launch(void* const* d_in, const int* in_sizes, int n_in,
                              void* d_out, int out_size)
{
    const float* query     = (const float*)d_in[0];
    const float* key_value = (const float*)d_in[1];
    const float* Wq = (const float*)d_in[2];
    const float* bq = (const float*)d_in[3];
    const float* Wk = (const float*)d_in[4];
    const float* bk = (const float*)d_in[5];
    const float* Wv = (const float*)d_in[6];
    const float* bv = (const float*)d_in[7];
    const float* Wo = (const float*)d_in[8];
    const float* bo = (const float*)d_in[9];
    float* out = (float*)d_out;

    float *gq, *gk, *gv, *gctx;
    cudaGetSymbolAddress((void**)&gq, g_q);
    cudaGetSymbolAddress((void**)&gk, g_k);
    cudaGetSymbolAddress((void**)&gv, g_v);
    cudaGetSymbolAddress((void**)&gctx, g_ctx);

    const dim3 gemm_grid(Eq / 128, (NB * SL) / 128);  // (8, 64)

    // Projections with fused head-transpose
    gemm_kernel<0><<<gemm_grid, 256>>>(query,     Wq, bq, gq);
    gemm_kernel<0><<<gemm_grid, 256>>>(key_value, Wk, bk, gk);
    gemm_kernel<0><<<gemm_grid, 256>>>(key_value, Wv, bv, gv);

    // Fused stablemax attention
    cudaFuncSetAttribute(attn_kernel, cudaFuncAttributeMaxDynamicSharedMemorySize,
                         ATTN_SMEM_BYTES);
    attn_kernel<<<dim3(SL / 128, NB * NH), 256, ATTN_SMEM_BYTES>>>(gq, gk, gv, gctx);

    // Output projection (flat)
    gemm_kernel<1><<<gemm_grid, 256>>>(gctx, Wo, bo, out);
}

// round 2
// speedup vs baseline: 2.0213x; 2.0213x over previous
#include <cuda_runtime.h>

// Problem constants
#define Eq 1024
#define NH 16
#define DH 64
#define NB 4
#define SL 2048

// Scratch (alloc-free rule: __device__ globals)
__device__ float g_q[NB * NH * SL * DH];
__device__ float g_k[NB * NH * SL * DH];
__device__ float g_v[NB * NH * SL * DH];
__device__ float g_ctx[NB * SL * Eq];

__device__ __forceinline__ unsigned f2tf(float x) {
    unsigned r;
    asm("cvt.rna.tf32.f32 %0, %1;" : "=r"(r) : "f"(x));
    return r;
}

__device__ __forceinline__ void mma8(float* c, const unsigned* a, const unsigned* b) {
    asm volatile(
        "mma.sync.aligned.m16n8k8.row.col.f32.tf32.tf32.f32 "
        "{%0,%1,%2,%3}, {%4,%5,%6,%7}, {%8,%9}, {%0,%1,%2,%3};"
        : "+f"(c[0]), "+f"(c[1]), "+f"(c[2]), "+f"(c[3])
        : "r"(a[0]), "r"(a[1]), "r"(a[2]), "r"(a[3]), "r"(b[0]), "r"(b[1]));
}

// ---------------------------------------------------------------------------
// tf32 GEMM: out = A @ W^T + bias. A:[M,1024] row-major, W:[1024,1024] (N,K).
// MODE 0: write [B,H,S,HD]; MODE 1: flat [M,N].
// 128x128x16 tile, 256 threads (8 warps, 4x2), warp tile 32x64.
// ---------------------------------------------------------------------------
template <int MODE>
__global__ __launch_bounds__(256) void gemm_tf32(
    const float* __restrict__ A, const float* __restrict__ W,
    const float* __restrict__ bias, float* __restrict__ out)
{
    __shared__ unsigned As[16][132];   // [k][m]
    __shared__ unsigned Bs[16][132];   // [k][n]

    const int tid = threadIdx.x;
    const int m0 = blockIdx.y * 128, n0 = blockIdx.x * 128;
    const int w = tid >> 5, lane = tid & 31;
    const int wm = w >> 1, wn = w & 1;
    const int g = lane >> 2, q4 = lane & 3;

    // Global load mapping: 512 float4 per tile; thread handles idx tid, tid+256
    const int r0 = tid >> 2, kq = (tid & 3) * 4;
    const int r1 = r0 + 64;
    const float* Ap0 = A + (size_t)(m0 + r0) * 1024 + kq;
    const float* Ap1 = A + (size_t)(m0 + r1) * 1024 + kq;
    const float* Wp0 = W + (size_t)(n0 + r0) * 1024 + kq;
    const float* Wp1 = W + (size_t)(n0 + r1) * 1024 + kq;

    float acc[2][8][4];
#pragma unroll
    for (int i = 0; i < 2; i++)
#pragma unroll
        for (int j = 0; j < 8; j++)
#pragma unroll
            for (int l = 0; l < 4; l++) acc[i][j][l] = 0.0f;

    float4 av0 = *(const float4*)Ap0, av1 = *(const float4*)Ap1;
    float4 wv0 = *(const float4*)Wp0, wv1 = *(const float4*)Wp1;

    for (int k0 = 0; k0 < 1024; k0 += 16) {
        __syncthreads();
        As[kq + 0][r0] = f2tf(av0.x); As[kq + 1][r0] = f2tf(av0.y);
        As[kq + 2][r0] = f2tf(av0.z); As[kq + 3][r0] = f2tf(av0.w);
        As[kq + 0][r1] = f2tf(av1.x); As[kq + 1][r1] = f2tf(av1.y);
        As[kq + 2][r1] = f2tf(av1.z); As[kq + 3][r1] = f2tf(av1.w);
        Bs[kq + 0][r0] = f2tf(wv0.x); Bs[kq + 1][r0] = f2tf(wv0.y);
        Bs[kq + 2][r0] = f2tf(wv0.z); Bs[kq + 3][r0] = f2tf(wv0.w);
        Bs[kq + 0][r1] = f2tf(wv1.x); Bs[kq + 1][r1] = f2tf(wv1.y);
        Bs[kq + 2][r1] = f2tf(wv1.z); Bs[kq + 3][r1] = f2tf(wv1.w);
        __syncthreads();

        if (k0 + 16 < 1024) {
            av0 = *(const float4*)(Ap0 + k0 + 16);
            av1 = *(const float4*)(Ap1 + k0 + 16);
            wv0 = *(const float4*)(Wp0 + k0 + 16);
            wv1 = *(const float4*)(Wp1 + k0 + 16);
        }

#pragma unroll
        for (int ks = 0; ks < 16; ks += 8) {
            unsigned af[2][4], bf[8][2];
#pragma unroll
            for (int im = 0; im < 2; im++) {
                const int mr = wm * 32 + im * 16 + g;
                af[im][0] = As[ks + q4][mr];
                af[im][1] = As[ks + q4][mr + 8];
                af[im][2] = As[ks + q4 + 4][mr];
                af[im][3] = As[ks + q4 + 4][mr + 8];
            }
#pragma unroll
            for (int jn = 0; jn < 8; jn++) {
                const int nc = wn * 64 + jn * 8 + g;
                bf[jn][0] = Bs[ks + q4][nc];
                bf[jn][1] = Bs[ks + q4 + 4][nc];
            }
#pragma unroll
            for (int im = 0; im < 2; im++)
#pragma unroll
                for (int jn = 0; jn < 8; jn++)
                    mma8(acc[im][jn], af[im], bf[jn]);
        }
    }

    // Epilogue: bias + layout transform
#pragma unroll
    for (int im = 0; im < 2; im++) {
#pragma unroll
        for (int jn = 0; jn < 8; jn++) {
            const int gn = n0 + wn * 64 + jn * 8 + 2 * q4;
            const float2 bv = *(const float2*)(bias + gn);
#pragma unroll
            for (int h2 = 0; h2 < 2; h2++) {
                const int gm = m0 + wm * 32 + im * 16 + h2 * 8 + g;
                const float o0 = acc[im][jn][2 * h2] + bv.x;
                const float o1 = acc[im][jn][2 * h2 + 1] + bv.y;
                if (MODE == 0) {
                    const int bb = gm >> 11, ss = gm & 2047;
                    const int hh = gn >> 6, dd = gn & 63;
                    *(float2*)(out + (((size_t)(bb * NH + hh)) * SL + ss) * DH + dd) =
                        make_float2(o0, o1);
                } else {
                    *(float2*)(out + (size_t)gm * Eq + gn) = make_float2(o0, o1);
                }
            }
        }
    }
}

// ---------------------------------------------------------------------------
// Fused stablemax attention on tf32 tensor cores.
// Block: 128 q-rows of one (b,h), 256 threads (8 warps: wm 0..3, wn 0..1).
// Per 64-kv tile: S = Q K^T (warp tile 32x32), stablemax numerator -> Ts (tf32),
// per-thread denom partials in regs; GEMM2 k-split across wn with end reduce.
// ---------------------------------------------------------------------------
#define SP 68
#define ATTN_SMEM_BYTES ((384 * SP) * 4 + 512)

__global__ __launch_bounds__(256) void attn_tf32(
    const float* __restrict__ qg, const float* __restrict__ kg,
    const float* __restrict__ vg, float* __restrict__ ctx)
{
    extern __shared__ unsigned sm[];
    unsigned* Qs = sm;                    // [128][SP]
    unsigned* Ts = Qs + 128 * SP;         // [128][SP]
    unsigned* Ks = Ts + 128 * SP;         // [64][SP]
    unsigned* Vs = Ks + 64 * SP;          // [64][SP]
    float* dsum = (float*)(Vs + 64 * SP); // [128]

    const int tid = threadIdx.x;
    const int w = tid >> 5, lane = tid & 31;
    const int wm = w >> 1, wn = w & 1;
    const int g = lane >> 2, q4 = lane & 3;
    const int bh = blockIdx.y, q0 = blockIdx.x * 128;
    const int mr0 = wm * 32 + g;

    const float* qb = qg + ((size_t)bh * SL + q0) * DH;
    const float* kb = kg + (size_t)bh * SL * DH;
    const float* vb = vg + (size_t)bh * SL * DH;

    // Load Q tile (128x64), convert to tf32
    for (int i = tid; i < 2048; i += 256) {
        const int row = i >> 4, c4 = (i & 15) * 4;
        float4 t = *(const float4*)(qb + row * DH + c4);
        Qs[row * SP + c4 + 0] = f2tf(t.x);
        Qs[row * SP + c4 + 1] = f2tf(t.y);
        Qs[row * SP + c4 + 2] = f2tf(t.z);
        Qs[row * SP + c4 + 3] = f2tf(t.w);
    }
    if (tid < 128) dsum[tid] = 0.0f;

    float oacc[2][8][4];
#pragma unroll
    for (int i = 0; i < 2; i++)
#pragma unroll
        for (int j = 0; j < 8; j++)
#pragma unroll
            for (int l = 0; l < 4; l++) oacc[i][j][l] = 0.0f;
    float dpart[2][2] = {{0.0f, 0.0f}, {0.0f, 0.0f}};

    for (int kv0 = 0; kv0 < SL; kv0 += 64) {
        __syncthreads();
        for (int i = tid; i < 1024; i += 256) {
            const int row = i >> 4, c4 = (i & 15) * 4;
            float4 kt = *(const float4*)(kb + (size_t)(kv0 + row) * DH + c4);
            Ks[row * SP + c4 + 0] = f2tf(kt.x);
            Ks[row * SP + c4 + 1] = f2tf(kt.y);
            Ks[row * SP + c4 + 2] = f2tf(kt.z);
            Ks[row * SP + c4 + 3] = f2tf(kt.w);
            float4 vt = *(const float4*)(vb + (size_t)(kv0 + row) * DH + c4);
            Vs[row * SP + c4 + 0] = f2tf(vt.x);
            Vs[row * SP + c4 + 1] = f2tf(vt.y);
            Vs[row * SP + c4 + 2] = f2tf(vt.z);
            Vs[row * SP + c4 + 3] = f2tf(vt.w);
        }
        __syncthreads();

        // GEMM1: S(32m x 32n per warp) = Q K^T, k = 64
        float sacc[2][4][4];
#pragma unroll
        for (int i = 0; i < 2; i++)
#pragma unroll
            for (int j = 0; j < 4; j++)
#pragma unroll
                for (int l = 0; l < 4; l++) sacc[i][j][l] = 0.0f;

#pragma unroll
        for (int ks = 0; ks < 64; ks += 8) {
            unsigned af[2][4], bf[4][2];
#pragma unroll
            for (int im = 0; im < 2; im++) {
                const int mr = mr0 + im * 16;
                af[im][0] = Qs[mr * SP + ks + q4];
                af[im][1] = Qs[(mr + 8) * SP + ks + q4];
                af[im][2] = Qs[mr * SP + ks + q4 + 4];
                af[im][3] = Qs[(mr + 8) * SP + ks + q4 + 4];
            }
#pragma unroll
            for (int jn = 0; jn < 4; jn++) {
                const int nc = wn * 32 + jn * 8 + g;
                bf[jn][0] = Ks[nc * SP + ks + q4];
                bf[jn][1] = Ks[nc * SP + ks + q4 + 4];
            }
#pragma unroll
            for (int im = 0; im < 2; im++)
#pragma unroll
                for (int jn = 0; jn < 4; jn++)
                    mma8(sacc[im][jn], af[im], bf[jn]);
        }

        // Stablemax numerator, denom partials, write T (tf32) to smem
#pragma unroll
        for (int im = 0; im < 2; im++) {
#pragma unroll
            for (int jn = 0; jn < 4; jn++) {
                const int c = wn * 32 + jn * 8 + 2 * q4;
#pragma unroll
                for (int h2 = 0; h2 < 2; h2++) {
                    const int r = mr0 + im * 16 + 8 * h2;
                    const float s0 = sacc[im][jn][2 * h2] * 0.125f;
                    const float s1 = sacc[im][jn][2 * h2 + 1] * 0.125f;
                    const float t0 = (s0 >= 0.0f) ? (s0 + 1.0f) : __fdividef(1.0f, 1.0f - s0);
                    const float t1 = (s1 >= 0.0f) ? (s1 + 1.0f) : __fdividef(1.0f, 1.0f - s1);
                    dpart[im][h2] += t0 + t1;
                    Ts[r * SP + c] = f2tf(t0);
                    Ts[r * SP + c + 1] = f2tf(t1);
                }
            }
        }
        __syncthreads();

        // GEMM2: oacc(32m x 64dv per warp) += T V, this warp's k-slice = 32
#pragma unroll
        for (int ks = 0; ks < 32; ks += 8) {
            const int kk = wn * 32 + ks;
            unsigned af[2][4], bf[8][2];
#pragma unroll
            for (int im = 0; im < 2; im++) {
                const int mr = mr0 + im * 16;
                af[im][0] = Ts[mr * SP + kk + q4];
                af[im][1] = Ts[(mr + 8) * SP + kk + q4];
                af[im][2] = Ts[mr * SP + kk + q4 + 4];
                af[im][3] = Ts[(mr + 8) * SP + kk + q4 + 4];
            }
#pragma unroll
            for (int jn = 0; jn < 8; jn++) {
                const int dv = jn * 8 + g;
                bf[jn][0] = Vs[(kk + q4) * SP + dv];
                bf[jn][1] = Vs[(kk + q4 + 4) * SP + dv];
            }
#pragma unroll
            for (int im = 0; im < 2; im++)
#pragma unroll
                for (int jn = 0; jn < 8; jn++)
                    mma8(oacc[im][jn], af[im], bf[jn]);
        }
    }

    // Denominator: quad-reduce then smem atomic across wn
#pragma unroll
    for (int off = 1; off < 4; off <<= 1) {
#pragma unroll
        for (int im = 0; im < 2; im++)
#pragma unroll
            for (int h2 = 0; h2 < 2; h2++)
                dpart[im][h2] += __shfl_xor_sync(0xffffffffu, dpart[im][h2], off);
    }
    if (q4 == 0) {
#pragma unroll
        for (int im = 0; im < 2; im++)
#pragma unroll
            for (int h2 = 0; h2 < 2; h2++)
                atomicAdd(&dsum[wm * 32 + im * 16 + 8 * h2 + g], dpart[im][h2]);
    }
    __syncthreads();

    // Cross-warp oacc reduce (wn=1 spills into Qs region, wn=0 finishes)
    float* red = (float*)Qs;  // [128][SP]
    if (wn == 1) {
#pragma unroll
        for (int im = 0; im < 2; im++)
#pragma unroll
            for (int jn = 0; jn < 8; jn++)
#pragma unroll
                for (int h2 = 0; h2 < 2; h2++) {
                    const int r = mr0 + im * 16 + 8 * h2;
                    const int c = jn * 8 + 2 * q4;
                    red[r * SP + c]     = oacc[im][jn][2 * h2];
                    red[r * SP + c + 1] = oacc[im][jn][2 * h2 + 1];
                }
    }
    __syncthreads();
    if (wn == 0) {
        const int b = bh >> 4, h = bh & 15;
#pragma unroll
        for (int im = 0; im < 2; im++) {
#pragma unroll
            for (int h2 = 0; h2 < 2; h2++) {
                const int m = mr0 + im * 16 + 8 * h2;
                const float inv = 1.0f / dsum[m];
                const size_t base = ((size_t)b * SL + q0 + m) * Eq + h * DH;
#pragma unroll
                for (int jn = 0; jn < 8; jn++) {
                    const int c = jn * 8 + 2 * q4;
                    const float o0 = (oacc[im][jn][2 * h2]     + red[m * SP + c])     * inv;
                    const float o1 = (oacc[im][jn][2 * h2 + 1] + red[m * SP + c + 1]) * inv;
                    *(float2*)(ctx + base + c) = make_float2(o0, o1);
                }
            }
        }
    }
}

// ---------------------------------------------------------------------------
extern "C" void kernel_launch(void* const* d_in, const int* in_sizes, int n_in,
                              void* d_out, int out_size)
{
    const float* query     = (const float*)d_in[0];
    const float* key_value = (const float*)d_in[1];
    const float* Wq = (const float*)d_in[2];
    const float* bq = (const float*)d_in[3];
    const float* Wk = (const float*)d_in[4];
    const float* bk = (const float*)d_in[5];
    const float* Wv = (const float*)d_in[6];
    const float* bv = (const float*)d_in[7];
    const float* Wo = (const float*)d_in[8];
    const float* bo = (const float*)d_in[9];
    float* out = (float*)d_out;

    float *gq, *gk, *gv, *gctx;
    cudaGetSymbolAddress((void**)&gq, g_q);
    cudaGetSymbolAddress((void**)&gk, g_k);
    cudaGetSymbolAddress((void**)&gv, g_v);
    cudaGetSymbolAddress((void**)&gctx, g_ctx);

    const dim3 gemm_grid(Eq / 128, (NB * SL) / 128);  // (8, 64)

    gemm_tf32<0><<<gemm_grid, 256>>>(query,     Wq, bq, gq);
    gemm_tf32<0><<<gemm_grid, 256>>>(key_value, Wk, bk, gk);
    gemm_tf32<0><<<gemm_grid, 256>>>(key_value, Wv, bv, gv);

    cudaFuncSetAttribute(attn_tf32, cudaFuncAttributeMaxDynamicSharedMemorySize,
                         ATTN_SMEM_BYTES);
    attn_tf32<<<dim3(SL / 128, NB * NH), 256, ATTN_SMEM_BYTES>>>(gq, gk, gv, gctx);

    gemm_tf32<1><<<gemm_grid, 256>>>(gctx, Wo, bo, out);
}

// round 3
// speedup vs baseline: 2.8870x; 1.4283x over previous
#include <cuda_runtime.h>

#define Eq 1024
#define NH 16
#define DH 64
#define NB 4
#define SL 2048

// Scratch (__device__ globals; alloc-free rule)
__device__ unsigned g_qc[NB * SL * Eq];     // tf32(query)
__device__ unsigned g_kvc[NB * SL * Eq];    // tf32(key_value)
__device__ unsigned g_wq[Eq * Eq], g_wk[Eq * Eq], g_wv[Eq * Eq], g_wo[Eq * Eq];
__device__ unsigned g_q[NB * NH * SL * DH]; // tf32 bits, [B,H,S,HD]
__device__ unsigned g_k[NB * NH * SL * DH];
__device__ unsigned g_v[NB * NH * SL * DH];
__device__ unsigned g_ctx[NB * SL * Eq];    // tf32 bits, [B,S,E]

__device__ __forceinline__ unsigned f2tf(float x) {
    unsigned r;
    asm("cvt.rna.tf32.f32 %0, %1;" : "=r"(r) : "f"(x));
    return r;
}

__device__ __forceinline__ void mma8(float* c, const unsigned* a, const unsigned* b) {
    asm volatile(
        "mma.sync.aligned.m16n8k8.row.col.f32.tf32.tf32.f32 "
        "{%0,%1,%2,%3}, {%4,%5,%6,%7}, {%8,%9}, {%0,%1,%2,%3};"
        : "+f"(c[0]), "+f"(c[1]), "+f"(c[2]), "+f"(c[3])
        : "r"(a[0]), "r"(a[1]), "r"(a[2]), "r"(a[3]), "r"(b[0]), "r"(b[1]));
}

__device__ __forceinline__ void cp16(unsigned smem_u32, const void* gptr) {
    asm volatile("cp.async.cg.shared.global [%0], [%1], 16;" :: "r"(smem_u32), "l"(gptr));
}
#define CP_COMMIT() asm volatile("cp.async.commit_group;")
#define CP_WAIT0()  asm volatile("cp.async.wait_group 0;")

// ---------------------------------------------------------------------------
// fp32 -> tf32-bits converter (bandwidth-bound, one pass over inputs/weights)
// ---------------------------------------------------------------------------
__global__ void cvt_tf32(const float4* __restrict__ src, uint4* __restrict__ dst, int n4) {
    for (int i = blockIdx.x * blockDim.x + threadIdx.x; i < n4; i += gridDim.x * blockDim.x) {
        float4 s = src[i];
        uint4 d;
        d.x = f2tf(s.x); d.y = f2tf(s.y); d.z = f2tf(s.z); d.w = f2tf(s.w);
        dst[i] = d;
    }
}

// ---------------------------------------------------------------------------
// tf32 GEMM: out = A @ W^T + bias. A,W already tf32 bits, K-major.
// 128x128x16 tile, 256 thr (8 warps 4x2), warp 32x64. cp.async 2-stage.
// MODE 0: write [B,H,S,HD] tf32 bits; MODE 1: flat fp32 [M,N].
// ---------------------------------------------------------------------------
#define GP 20  // [m][k] pitch: banks (20g+q4) mod 32 all-distinct

template <int MODE>
__global__ __launch_bounds__(256, 2) void gemm_tf32(
    const unsigned* __restrict__ A, const unsigned* __restrict__ W,
    const float* __restrict__ bias, float* __restrict__ out)
{
    __shared__ unsigned As[2][128 * GP];
    __shared__ unsigned Bs[2][128 * GP];

    const int tid = threadIdx.x;
    const int m0 = blockIdx.y * 128, n0 = blockIdx.x * 128;
    const int w = tid >> 5, lane = tid & 31;
    const int wm = w >> 1, wn = w & 1;
    const int g = lane >> 2, q4 = lane & 3;

    // copy mapping: 512 16B-chunks per operand per stage; thread does idx tid, tid+256
    const int r0 = tid >> 2, kq = (tid & 3) * 4;
    const int r1 = r0 + 64;

    unsigned sA, sB;
    {
        unsigned gen = (unsigned)__cvta_generic_to_shared(&As[0][0]);
        sA = gen;
        sB = (unsigned)__cvta_generic_to_shared(&Bs[0][0]);
    }
    const unsigned stageBytes = 128 * GP * 4;

    float acc[2][8][4];
#pragma unroll
    for (int i = 0; i < 2; i++)
#pragma unroll
        for (int j = 0; j < 8; j++)
#pragma unroll
            for (int l = 0; l < 4; l++) acc[i][j][l] = 0.0f;

    auto issue = [&](int t) {
        const int s = t & 1;
        const int kb = t * 16 + kq;
        cp16(sA + s * stageBytes + (r0 * GP + kq) * 4, A + (size_t)(m0 + r0) * 1024 + kb);
        cp16(sA + s * stageBytes + (r1 * GP + kq) * 4, A + (size_t)(m0 + r1) * 1024 + kb);
        cp16(sB + s * stageBytes + (r0 * GP + kq) * 4, W + (size_t)(n0 + r0) * 1024 + kb);
        cp16(sB + s * stageBytes + (r1 * GP + kq) * 4, W + (size_t)(n0 + r1) * 1024 + kb);
        CP_COMMIT();
    };

    issue(0);
    for (int t = 0; t < 64; t++) {
        CP_WAIT0();
        __syncthreads();
        if (t < 63) issue(t + 1);
        const unsigned* as = &As[t & 1][0];
        const unsigned* bs = &Bs[t & 1][0];
#pragma unroll
        for (int ks = 0; ks < 16; ks += 8) {
            unsigned af[2][4], bf[8][2];
#pragma unroll
            for (int im = 0; im < 2; im++) {
                const int mr = wm * 32 + im * 16 + g;
                af[im][0] = as[mr * GP + ks + q4];
                af[im][1] = as[(mr + 8) * GP + ks + q4];
                af[im][2] = as[mr * GP + ks + q4 + 4];
                af[im][3] = as[(mr + 8) * GP + ks + q4 + 4];
            }
#pragma unroll
            for (int jn = 0; jn < 8; jn++) {
                const int nc = wn * 64 + jn * 8 + g;
                bf[jn][0] = bs[nc * GP + ks + q4];
                bf[jn][1] = bs[nc * GP + ks + q4 + 4];
            }
#pragma unroll
            for (int im = 0; im < 2; im++)
#pragma unroll
                for (int jn = 0; jn < 8; jn++)
                    mma8(acc[im][jn], af[im], bf[jn]);
        }
        __syncthreads();
    }

#pragma unroll
    for (int im = 0; im < 2; im++) {
#pragma unroll
        for (int jn = 0; jn < 8; jn++) {
            const int gn = n0 + wn * 64 + jn * 8 + 2 * q4;
            const float2 bv = *(const float2*)(bias + gn);
#pragma unroll
            for (int h2 = 0; h2 < 2; h2++) {
                const int gm = m0 + wm * 32 + im * 16 + h2 * 8 + g;
                const float o0 = acc[im][jn][2 * h2] + bv.x;
                const float o1 = acc[im][jn][2 * h2 + 1] + bv.y;
                if (MODE == 0) {
                    const int bb = gm >> 11, ss = gm & 2047;
                    const int hh = gn >> 6, dd = gn & 63;
                    uint2 bits = make_uint2(f2tf(o0), f2tf(o1));
                    *(uint2*)((unsigned*)out + (((size_t)(bb * NH + hh)) * SL + ss) * DH + dd) = bits;
                } else {
                    *(float2*)(out + (size_t)gm * Eq + gn) = make_float2(o0, o1);
                }
            }
        }
    }
}

// ---------------------------------------------------------------------------
// Fused stablemax attention, tf32 mma, cp.async double-buffered K/V.
// 128 q-rows per block, 256 thr (4 wm x 2 wn). GEMM1: 32m x 32n (n-split).
// GEMM2: 32m x 32dv (dv-split, full k=64) -> no cross-warp output reduce.
// ---------------------------------------------------------------------------
#define SP 68
#define ATTN_SMEM_BYTES ((128 * SP * 2 + 64 * SP * 4 + 128) * 4)

__global__ __launch_bounds__(256) void attn_tf32(
    const unsigned* __restrict__ qg, const unsigned* __restrict__ kg,
    const unsigned* __restrict__ vg, unsigned* __restrict__ ctx)
{
    extern __shared__ unsigned sm[];
    unsigned* Qs = sm;                         // [128][SP]
    unsigned* Ts = Qs + 128 * SP;              // [128][SP]
    unsigned* Ks = Ts + 128 * SP;              // [2][64][SP]
    unsigned* Vs = Ks + 2 * 64 * SP;           // [2][64][SP]
    float* dsum = (float*)(Vs + 2 * 64 * SP);  // [128]

    const int tid = threadIdx.x;
    const int w = tid >> 5, lane = tid & 31;
    const int wm = w >> 1, wn = w & 1;
    const int g = lane >> 2, q4 = lane & 3;
    const int bh = blockIdx.y, q0 = blockIdx.x * 128;
    const int mr0 = wm * 32 + g;

    const unsigned* qb = qg + ((size_t)bh * SL + q0) * DH;
    const unsigned* kb = kg + (size_t)bh * SL * DH;
    const unsigned* vb = vg + (size_t)bh * SL * DH;

    const unsigned sQ = (unsigned)__cvta_generic_to_shared(Qs);
    const unsigned sK = (unsigned)__cvta_generic_to_shared(Ks);
    const unsigned sV = (unsigned)__cvta_generic_to_shared(Vs);
    const unsigned kvStage = 64 * SP * 4;

    auto issue_kv = [&](int t) {
        const int s = t & 1;
        const int kv0 = t * 64;
#pragma unroll
        for (int i = 0; i < 4; i++) {
            const int idx = tid + i * 256;      // 0..1023
            const int row = idx >> 4, c4 = (idx & 15) * 4;
            cp16(sK + s * kvStage + (row * SP + c4) * 4, kb + (size_t)(kv0 + row) * DH + c4);
            cp16(sV + s * kvStage + (row * SP + c4) * 4, vb + (size_t)(kv0 + row) * DH + c4);
        }
        CP_COMMIT();
    };

    // Prologue: Q tile + K0/V0
#pragma unroll
    for (int i = 0; i < 8; i++) {
        const int idx = tid + i * 256;          // 0..2047
        const int row = idx >> 4, c4 = (idx & 15) * 4;
        cp16(sQ + (row * SP + c4) * 4, qb + (size_t)row * DH + c4);
    }
    CP_COMMIT();
    issue_kv(0);
    if (tid < 128) dsum[tid] = 0.0f;
    CP_WAIT0();
    __syncthreads();

    float oacc[2][4][4];
#pragma unroll
    for (int i = 0; i < 2; i++)
#pragma unroll
        for (int j = 0; j < 4; j++)
#pragma unroll
            for (int l = 0; l < 4; l++) oacc[i][j][l] = 0.0f;
    float dpart[2][2] = {{0.0f, 0.0f}, {0.0f, 0.0f}};

    for (int t = 0; t < 32; t++) {
        const unsigned* ks_ = Ks + (t & 1) * 64 * SP;
        const unsigned* vs_ = Vs + (t & 1) * 64 * SP;
        if (t < 31) issue_kv(t + 1);  // flies under this tile's compute

        // GEMM1: S(32m x 32n) = Q K^T, k=64
        float sacc[2][4][4];
#pragma unroll
        for (int i = 0; i < 2; i++)
#pragma unroll
            for (int j = 0; j < 4; j++)
#pragma unroll
                for (int l = 0; l < 4; l++) sacc[i][j][l] = 0.0f;

#pragma unroll
        for (int ks = 0; ks < 64; ks += 8) {
            unsigned af[2][4], bf[4][2];
#pragma unroll
            for (int im = 0; im < 2; im++) {
                const int mr = mr0 + im * 16;
                af[im][0] = Qs[mr * SP + ks + q4];
                af[im][1] = Qs[(mr + 8) * SP + ks + q4];
                af[im][2] = Qs[mr * SP + ks + q4 + 4];
                af[im][3] = Qs[(mr + 8) * SP + ks + q4 + 4];
            }
#pragma unroll
            for (int jn = 0; jn < 4; jn++) {
                const int nc = wn * 32 + jn * 8 + g;
                bf[jn][0] = ks_[nc * SP + ks + q4];
                bf[jn][1] = ks_[nc * SP + ks + q4 + 4];
            }
#pragma unroll
            for (int im = 0; im < 2; im++)
#pragma unroll
                for (int jn = 0; jn < 4; jn++)
                    mma8(sacc[im][jn], af[im], bf[jn]);
        }

        // Stablemax numerator -> Ts (tf32), denom partials in regs
#pragma unroll
        for (int im = 0; im < 2; im++) {
#pragma unroll
            for (int jn = 0; jn < 4; jn++) {
                const int c = wn * 32 + jn * 8 + 2 * q4;
#pragma unroll
                for (int h2 = 0; h2 < 2; h2++) {
                    const int r = mr0 + im * 16 + 8 * h2;
                    const float s0 = sacc[im][jn][2 * h2] * 0.125f;
                    const float s1 = sacc[im][jn][2 * h2 + 1] * 0.125f;
                    const float t0 = (s0 >= 0.0f) ? (s0 + 1.0f) : __fdividef(1.0f, 1.0f - s0);
                    const float t1 = (s1 >= 0.0f) ? (s1 + 1.0f) : __fdividef(1.0f, 1.0f - s1);
                    dpart[im][h2] += t0 + t1;
                    Ts[r * SP + c] = f2tf(t0);
                    Ts[r * SP + c + 1] = f2tf(t1);
                }
            }
        }
        __syncthreads();  // Ts visible

        // GEMM2: oacc(32m x 32dv) += T V, full k=64
#pragma unroll
        for (int kk = 0; kk < 64; kk += 8) {
            unsigned af[2][4], bf[4][2];
#pragma unroll
            for (int im = 0; im < 2; im++) {
                const int mr = mr0 + im * 16;
                af[im][0] = Ts[mr * SP + kk + q4];
                af[im][1] = Ts[(mr + 8) * SP + kk + q4];
                af[im][2] = Ts[mr * SP + kk + q4 + 4];
                af[im][3] = Ts[(mr + 8) * SP + kk + q4 + 4];
            }
#pragma unroll
            for (int jn = 0; jn < 4; jn++) {
                const int dv = wn * 32 + jn * 8 + g;
                bf[jn][0] = vs_[(kk + q4) * SP + dv];
                bf[jn][1] = vs_[(kk + q4 + 4) * SP + dv];
            }
#pragma unroll
            for (int im = 0; im < 2; im++)
#pragma unroll
                for (int jn = 0; jn < 4; jn++)
                    mma8(oacc[im][jn], af[im], bf[jn]);
        }
        CP_WAIT0();       // next K/V landed
        __syncthreads();  // Ts + Vs[b] free for reuse
    }

    // Denominator: quad-shuffle reduce then atomic across wn
#pragma unroll
    for (int off = 1; off < 4; off <<= 1)
#pragma unroll
        for (int im = 0; im < 2; im++)
#pragma unroll
            for (int h2 = 0; h2 < 2; h2++)
                dpart[im][h2] += __shfl_xor_sync(0xffffffffu, dpart[im][h2], off);
    if (q4 == 0)
#pragma unroll
        for (int im = 0; im < 2; im++)
#pragma unroll
            for (int h2 = 0; h2 < 2; h2++)
                atomicAdd(&dsum[wm * 32 + im * 16 + 8 * h2 + g], dpart[im][h2]);
    __syncthreads();

    // Write ctx as tf32 bits (consumed by output GEMM)
    const int b = bh >> 4, h = bh & 15;
#pragma unroll
    for (int im = 0; im < 2; im++) {
#pragma unroll
        for (int h2 = 0; h2 < 2; h2++) {
            const int m = mr0 + im * 16 + 8 * h2;
            const float inv = 1.0f / dsum[m];
            const size_t base = ((size_t)b * SL + q0 + m) * Eq + h * DH;
#pragma unroll
            for (int jn = 0; jn < 4; jn++) {
                const int c = wn * 32 + jn * 8 + 2 * q4;
                uint2 bits = make_uint2(f2tf(oacc[im][jn][2 * h2] * inv),
                                        f2tf(oacc[im][jn][2 * h2 + 1] * inv));
                *(uint2*)(ctx + base + c) = bits;
            }
        }
    }
}

// ---------------------------------------------------------------------------
extern "C" void kernel_launch(void* const* d_in, const int* in_sizes, int n_in,
                              void* d_out, int out_size)
{
    const float* query     = (const float*)d_in[0];
    const float* key_value = (const float*)d_in[1];
    const float* Wq = (const float*)d_in[2];
    const float* bq = (const float*)d_in[3];
    const float* Wk = (const float*)d_in[4];
    const float* bk = (const float*)d_in[5];
    const float* Wv = (const float*)d_in[6];
    const float* bv = (const float*)d_in[7];
    const float* Wo = (const float*)d_in[8];
    const float* bo = (const float*)d_in[9];
    float* out = (float*)d_out;

    unsigned *qc, *kvc, *wq, *wk, *wv, *wo, *gq, *gk, *gv, *gctx;
    cudaGetSymbolAddress((void**)&qc,  g_qc);
    cudaGetSymbolAddress((void**)&kvc, g_kvc);
    cudaGetSymbolAddress((void**)&wq,  g_wq);
    cudaGetSymbolAddress((void**)&wk,  g_wk);
    cudaGetSymbolAddress((void**)&wv,  g_wv);
    cudaGetSymbolAddress((void**)&wo,  g_wo);
    cudaGetSymbolAddress((void**)&gq,  g_q);
    cudaGetSymbolAddress((void**)&gk,  g_k);
    cudaGetSymbolAddress((void**)&gv,  g_v);
    cudaGetSymbolAddress((void**)&gctx, g_ctx);

    const int nBig4 = NB * SL * Eq / 4, nW4 = Eq * Eq / 4;
    cvt_tf32<<<2048, 256>>>((const float4*)query,     (uint4*)qc,  nBig4);
    cvt_tf32<<<2048, 256>>>((const float4*)key_value, (uint4*)kvc, nBig4);
    cvt_tf32<<<1024, 256>>>((const float4*)Wq, (uint4*)wq, nW4);
    cvt_tf32<<<1024, 256>>>((const float4*)Wk, (uint4*)wk, nW4);
    cvt_tf32<<<1024, 256>>>((const float4*)Wv, (uint4*)wv, nW4);
    cvt_tf32<<<1024, 256>>>((const float4*)Wo, (uint4*)wo, nW4);

    const dim3 gemm_grid(Eq / 128, (NB * SL) / 128);  // (8, 64)
    gemm_tf32<0><<<gemm_grid, 256>>>(qc,  wq, bq, (float*)gq);
    gemm_tf32<0><<<gemm_grid, 256>>>(kvc, wk, bk, (float*)gk);
    gemm_tf32<0><<<gemm_grid, 256>>>(kvc, wv, bv, (float*)gv);

    cudaFuncSetAttribute(attn_tf32, cudaFuncAttributeMaxDynamicSharedMemorySize,
                         ATTN_SMEM_BYTES);
    attn_tf32<<<dim3(SL / 128, NB * NH), 256, ATTN_SMEM_BYTES>>>(gq, gk, gv, gctx);

    gemm_tf32<1><<<gemm_grid, 256>>>(gctx, wo, bo, out);
}

// round 4
// speedup vs baseline: 6.1389x; 2.1264x over previous
#include <cuda_runtime.h>
#include <cuda_fp16.h>

#define Eq 1024
#define NH 16
#define DH 64
#define NB 4
#define SL 2048

// Scratch (__device__ globals; alloc-free rule). All fp16 packed as u32 pairs.
__device__ unsigned g_qc[NB * SL * Eq / 2];      // fp16(query)
__device__ unsigned g_kvc[NB * SL * Eq / 2];     // fp16(key_value)
__device__ unsigned g_wq[Eq * Eq / 2], g_wk[Eq * Eq / 2];
__device__ unsigned g_wv[Eq * Eq / 2], g_wo[Eq * Eq / 2];
__device__ unsigned g_q[NB * NH * SL * DH / 2];  // [B,H,S,HD] fp16
__device__ unsigned g_k[NB * NH * SL * DH / 2];  // [B,H,S,HD] fp16
__device__ unsigned g_vt[NB * NH * SL * DH / 2]; // [B,H,HD,S] fp16 (transposed!)
__device__ unsigned g_ctx[NB * SL * Eq / 2];     // [B,S,E] fp16

__device__ __forceinline__ unsigned pkh2(float a, float b) {
    __half2 h = __floats2half2_rn(a, b);
    return *(unsigned*)&h;
}

__device__ __forceinline__ void mma16(float* c, const unsigned* a, const unsigned* b) {
    asm volatile(
        "mma.sync.aligned.m16n8k16.row.col.f32.f16.f16.f32 "
        "{%0,%1,%2,%3}, {%4,%5,%6,%7}, {%8,%9}, {%0,%1,%2,%3};"
        : "+f"(c[0]), "+f"(c[1]), "+f"(c[2]), "+f"(c[3])
        : "r"(a[0]), "r"(a[1]), "r"(a[2]), "r"(a[3]), "r"(b[0]), "r"(b[1]));
}

__device__ __forceinline__ void cp16(unsigned smem_u32, const void* gptr) {
    asm volatile("cp.async.cg.shared.global [%0], [%1], 16;" :: "r"(smem_u32), "l"(gptr));
}
#define CP_COMMIT() asm volatile("cp.async.commit_group;")
#define CP_WAIT0()  asm volatile("cp.async.wait_group 0;")

// ---------------------------------------------------------------------------
// fp32 -> fp16-packed converter
// ---------------------------------------------------------------------------
__global__ void cvt_f16(const float4* __restrict__ src, uint2* __restrict__ dst, int n4) {
    for (int i = blockIdx.x * blockDim.x + threadIdx.x; i < n4; i += gridDim.x * blockDim.x) {
        float4 s = src[i];
        dst[i] = make_uint2(pkh2(s.x, s.y), pkh2(s.z, s.w));
    }
}

// ---------------------------------------------------------------------------
// fp16 GEMM: out = A @ W^T + bias. A,W fp16-packed u32, K-major (512 u32/row).
// 128x128x32 tile, 256 thr (8 warps 4x2), warp 32x64. cp.async 2-stage.
// MODE 0: [B,H,S,HD] fp16; MODE 1: flat fp32; MODE 2: [B,H,HD,S] fp16 transposed.
// ---------------------------------------------------------------------------
#define GP 20  // u32 pitch per row (16 used)

template <int MODE>
__global__ __launch_bounds__(256, 2) void gemm_f16(
    const unsigned* __restrict__ A, const unsigned* __restrict__ W,
    const float* __restrict__ bias, float* __restrict__ out)
{
    __shared__ unsigned As[2][128 * GP];
    __shared__ unsigned Bs[2][128 * GP];

    const int tid = threadIdx.x;
    const int m0 = blockIdx.y * 128, n0 = blockIdx.x * 128;
    const int w = tid >> 5, lane = tid & 31;
    const int wm = w >> 1, wn = w & 1;
    const int g = lane >> 2, q4 = lane & 3;

    // copy mapping: per stage per operand 512 chunks (128 rows x 4x16B)
    const int r0 = tid >> 2, r1 = r0 + 64;
    const int kq = (tid & 3) * 4;

    const unsigned sA = (unsigned)__cvta_generic_to_shared(&As[0][0]);
    const unsigned sB = (unsigned)__cvta_generic_to_shared(&Bs[0][0]);
    const unsigned stageBytes = 128 * GP * 4;

    float acc[2][8][4];
#pragma unroll
    for (int i = 0; i < 2; i++)
#pragma unroll
        for (int j = 0; j < 8; j++)
#pragma unroll
            for (int l = 0; l < 4; l++) acc[i][j][l] = 0.0f;

    auto issue = [&](int t) {
        const int s = t & 1;
        const int kb = t * 16 + kq;  // u32 col in gmem row
        cp16(sA + s * stageBytes + (r0 * GP + kq) * 4, A + (size_t)(m0 + r0) * 512 + kb);
        cp16(sA + s * stageBytes + (r1 * GP + kq) * 4, A + (size_t)(m0 + r1) * 512 + kb);
        cp16(sB + s * stageBytes + (r0 * GP + kq) * 4, W + (size_t)(n0 + r0) * 512 + kb);
        cp16(sB + s * stageBytes + (r1 * GP + kq) * 4, W + (size_t)(n0 + r1) * 512 + kb);
        CP_COMMIT();
    };

    issue(0);
    for (int t = 0; t < 32; t++) {
        CP_WAIT0();
        __syncthreads();
        if (t < 31) issue(t + 1);
        const unsigned* as = &As[t & 1][0];
        const unsigned* bs = &Bs[t & 1][0];
#pragma unroll
        for (int kb4 = 0; kb4 < 16; kb4 += 8) {  // two k16 blocks
            unsigned af[2][4], bf[8][2];
#pragma unroll
            for (int im = 0; im < 2; im++) {
                const int mr = wm * 32 + im * 16 + g;
                af[im][0] = as[mr * GP + kb4 + q4];
                af[im][1] = as[(mr + 8) * GP + kb4 + q4];
                af[im][2] = as[mr * GP + kb4 + q4 + 4];
                af[im][3] = as[(mr + 8) * GP + kb4 + q4 + 4];
            }
#pragma unroll
            for (int jn = 0; jn < 8; jn++) {
                const int nc = wn * 64 + jn * 8 + g;
                bf[jn][0] = bs[nc * GP + kb4 + q4];
                bf[jn][1] = bs[nc * GP + kb4 + q4 + 4];
            }
#pragma unroll
            for (int im = 0; im < 2; im++)
#pragma unroll
                for (int jn = 0; jn < 8; jn++)
                    mma16(acc[im][jn], af[im], bf[jn]);
        }
    }

#pragma unroll
    for (int im = 0; im < 2; im++) {
#pragma unroll
        for (int jn = 0; jn < 8; jn++) {
            const int gn = n0 + wn * 64 + jn * 8 + 2 * q4;
            const float2 bv = *(const float2*)(bias + gn);
#pragma unroll
            for (int h2 = 0; h2 < 2; h2++) {
                const int gm = m0 + wm * 32 + im * 16 + h2 * 8 + g;
                const float o0 = acc[im][jn][2 * h2] + bv.x;
                const float o1 = acc[im][jn][2 * h2 + 1] + bv.y;
                const int bb = gm >> 11, ss = gm & 2047;
                const int hh = gn >> 6, dd = gn & 63;
                if (MODE == 0) {
                    ((unsigned*)out)[(((size_t)(bb * NH + hh)) * SL + ss) * 32 + (dd >> 1)] =
                        pkh2(o0, o1);
                } else if (MODE == 2) {
                    __half* vt = (__half*)out;
                    vt[(((size_t)(bb * NH + hh)) * DH + dd) * SL + ss] = __float2half_rn(o0);
                    vt[(((size_t)(bb * NH + hh)) * DH + dd + 1) * SL + ss] = __float2half_rn(o1);
                } else {
                    *(float2*)(out + (size_t)gm * Eq + gn) = make_float2(o0, o1);
                }
            }
        }
    }
}

// ---------------------------------------------------------------------------
// Fused stablemax attention, fp16 m16n8k16, register-resident T (FA2 identity),
// register denominators, V^T gmem layout, cp.async double-buffered K/V.
// 8 warps x 16 q-rows, full n=64 per warp. One __syncthreads per kv tile.
// ---------------------------------------------------------------------------
#define AP 36  // u32 pitch for 64-half rows (32 used)
#define ATTN_SMEM_BYTES ((128 * AP + 4 * 64 * AP) * 4)

__global__ __launch_bounds__(256, 2) void attn_f16(
    const unsigned* __restrict__ qg, const unsigned* __restrict__ kg,
    const unsigned* __restrict__ vtg, unsigned* __restrict__ ctx)
{
    extern __shared__ unsigned sm[];
    unsigned* Qs = sm;                // [128][AP]
    unsigned* Ks = Qs + 128 * AP;     // [2][64][AP]
    unsigned* Vs = Ks + 2 * 64 * AP;  // [2][64][AP]  rows = dv, cols = kv halfs

    const int tid = threadIdx.x;
    const int wm = tid >> 5, lane = tid & 31;
    const int g = lane >> 2, q4 = lane & 3;
    const int bh = blockIdx.y, q0 = blockIdx.x * 128;
    const int r_lo = wm * 16 + g, r_hi = r_lo + 8;

    const unsigned* qb = qg + ((size_t)bh * SL + q0) * 32;
    const unsigned* kb = kg + (size_t)bh * SL * 32;
    const unsigned* vtb = vtg + (size_t)bh * DH * (SL / 2);  // [64 rows][1024 u32]

    const unsigned sQ = (unsigned)__cvta_generic_to_shared(Qs);
    const unsigned sK = (unsigned)__cvta_generic_to_shared(Ks);
    const unsigned sV = (unsigned)__cvta_generic_to_shared(Vs);
    const unsigned kvStage = 64 * AP * 4;

    auto issue_kv = [&](int t) {
        const int s = t & 1;
        const int kv0 = t * 64;
#pragma unroll
        for (int i = 0; i < 2; i++) {
            const int idx = tid + i * 256;  // 0..511
            const int row = idx >> 3, c = (idx & 7) * 4;
            cp16(sK + s * kvStage + (row * AP + c) * 4, kb + (size_t)(kv0 + row) * 32 + c);
            cp16(sV + s * kvStage + (row * AP + c) * 4, vtb + (size_t)row * 1024 + (kv0 >> 1) + c);
        }
        CP_COMMIT();
    };

    // Prologue: Q tile + first K/V
#pragma unroll
    for (int i = 0; i < 4; i++) {
        const int idx = tid + i * 256;  // 0..1023
        const int row = idx >> 3, c = (idx & 7) * 4;
        cp16(sQ + (row * AP + c) * 4, qb + (size_t)row * 32 + c);
    }
    issue_kv(0);
    CP_WAIT0();
    __syncthreads();

    float oacc[8][4];
#pragma unroll
    for (int j = 0; j < 8; j++)
#pragma unroll
        for (int l = 0; l < 4; l++) oacc[j][l] = 0.0f;
    float dlo = 0.0f, dhi = 0.0f;

    // Q fragments are tile-invariant: hoist
    unsigned qf[4][4];
#pragma unroll
    for (int kb4 = 0; kb4 < 4; kb4++) {
        qf[kb4][0] = Qs[r_lo * AP + kb4 * 8 + q4];
        qf[kb4][1] = Qs[r_hi * AP + kb4 * 8 + q4];
        qf[kb4][2] = Qs[r_lo * AP + kb4 * 8 + q4 + 4];
        qf[kb4][3] = Qs[r_hi * AP + kb4 * 8 + q4 + 4];
    }

    for (int t = 0; t < 32; t++) {
        const unsigned* ks_ = Ks + (t & 1) * 64 * AP;
        const unsigned* vs_ = Vs + (t & 1) * 64 * AP;
        if (t < 31) issue_kv(t + 1);

        // GEMM1: S(16m x 64n) = Q K^T, k = 64 (4 k16 blocks)
        float sacc[8][4];
#pragma unroll
        for (int j = 0; j < 8; j++)
#pragma unroll
            for (int l = 0; l < 4; l++) sacc[j][l] = 0.0f;

#pragma unroll
        for (int kb4 = 0; kb4 < 4; kb4++) {
#pragma unroll
            for (int jn = 0; jn < 8; jn++) {
                const int nc = jn * 8 + g;
                unsigned bf[2];
                bf[0] = ks_[nc * AP + kb4 * 8 + q4];
                bf[1] = ks_[nc * AP + kb4 * 8 + q4 + 4];
                mma16(sacc[jn], qf[kb4], bf);
            }
        }

        // Stablemax numerator -> registers (packed as GEMM2 A-fragments)
        unsigned ta[8], tb[8];
#pragma unroll
        for (int jn = 0; jn < 8; jn++) {
            const float s0 = sacc[jn][0] * 0.125f;
            const float s1 = sacc[jn][1] * 0.125f;
            const float s2 = sacc[jn][2] * 0.125f;
            const float s3 = sacc[jn][3] * 0.125f;
            const float t0 = (s0 >= 0.0f) ? (s0 + 1.0f) : __fdividef(1.0f, 1.0f - s0);
            const float t1 = (s1 >= 0.0f) ? (s1 + 1.0f) : __fdividef(1.0f, 1.0f - s1);
            const float t2 = (s2 >= 0.0f) ? (s2 + 1.0f) : __fdividef(1.0f, 1.0f - s2);
            const float t3 = (s3 >= 0.0f) ? (s3 + 1.0f) : __fdividef(1.0f, 1.0f - s3);
            dlo += t0 + t1;
            dhi += t2 + t3;
            ta[jn] = pkh2(t0, t1);
            tb[jn] = pkh2(t2, t3);
        }

        // GEMM2: O(16m x 64dv) += T V, k = 64; A straight from registers
#pragma unroll
        for (int kb = 0; kb < 4; kb++) {
            unsigned af[4] = {ta[2 * kb], tb[2 * kb], ta[2 * kb + 1], tb[2 * kb + 1]};
#pragma unroll
            for (int jd = 0; jd < 8; jd++) {
                const int dv = jd * 8 + g;
                unsigned bf[2];
                bf[0] = vs_[dv * AP + kb * 8 + q4];
                bf[1] = vs_[dv * AP + kb * 8 + q4 + 4];
                mma16(oacc[jd], af, bf);
            }
        }

        CP_WAIT0();       // next K/V landed
        __syncthreads();  // everyone done reading buffer t&1
    }

    // Row denominators: quad all-reduce (4 lanes share each row)
#pragma unroll
    for (int off = 1; off < 4; off <<= 1) {
        dlo += __shfl_xor_sync(0xffffffffu, dlo, off);
        dhi += __shfl_xor_sync(0xffffffffu, dhi, off);
    }
    const float inv_lo = 1.0f / dlo, inv_hi = 1.0f / dhi;

    // Write ctx fp16 [B,S,E]
    const int b = bh >> 4, h = bh & 15;
    const size_t base_lo = ((size_t)b * SL + q0 + r_lo) * 512 + h * 32;
    const size_t base_hi = ((size_t)b * SL + q0 + r_hi) * 512 + h * 32;
#pragma unroll
    for (int jd = 0; jd < 8; jd++) {
        ctx[base_lo + jd * 4 + q4] = pkh2(oacc[jd][0] * inv_lo, oacc[jd][1] * inv_lo);
        ctx[base_hi + jd * 4 + q4] = pkh2(oacc[jd][2] * inv_hi, oacc[jd][3] * inv_hi);
    }
}

// ---------------------------------------------------------------------------
extern "C" void kernel_launch(void* const* d_in, const int* in_sizes, int n_in,
                              void* d_out, int out_size)
{
    const float* query     = (const float*)d_in[0];
    const float* key_value = (const float*)d_in[1];
    const float* Wq = (const float*)d_in[2];
    const float* bq = (const float*)d_in[3];
    const float* Wk = (const float*)d_in[4];
    const float* bk = (const float*)d_in[5];
    const float* Wv = (const float*)d_in[6];
    const float* bv = (const float*)d_in[7];
    const float* Wo = (const float*)d_in[8];
    const float* bo = (const float*)d_in[9];
    float* out = (float*)d_out;

    unsigned *qc, *kvc, *wq, *wk, *wv, *wo, *gq, *gk, *gvt, *gctx;
    cudaGetSymbolAddress((void**)&qc,  g_qc);
    cudaGetSymbolAddress((void**)&kvc, g_kvc);
    cudaGetSymbolAddress((void**)&wq,  g_wq);
    cudaGetSymbolAddress((void**)&wk,  g_wk);
    cudaGetSymbolAddress((void**)&wv,  g_wv);
    cudaGetSymbolAddress((void**)&wo,  g_wo);
    cudaGetSymbolAddress((void**)&gq,  g_q);
    cudaGetSymbolAddress((void**)&gk,  g_k);
    cudaGetSymbolAddress((void**)&gvt, g_vt);
    cudaGetSymbolAddress((void**)&gctx, g_ctx);

    const int nBig4 = NB * SL * Eq / 4, nW4 = Eq * Eq / 4;
    cvt_f16<<<2048, 256>>>((const float4*)query,     (uint2*)qc,  nBig4);
    cvt_f16<<<2048, 256>>>((const float4*)key_value, (uint2*)kvc, nBig4);
    cvt_f16<<<1024, 256>>>((const float4*)Wq, (uint2*)wq, nW4);
    cvt_f16<<<1024, 256>>>((const float4*)Wk, (uint2*)wk, nW4);
    cvt_f16<<<1024, 256>>>((const float4*)Wv, (uint2*)wv, nW4);
    cvt_f16<<<1024, 256>>>((const float4*)Wo, (uint2*)wo, nW4);

    const dim3 gemm_grid(Eq / 128, (NB * SL) / 128);  // (8, 64)
    gemm_f16<0><<<gemm_grid, 256>>>(qc,  wq, bq, (float*)gq);
    gemm_f16<0><<<gemm_grid, 256>>>(kvc, wk, bk, (float*)gk);
    gemm_f16<2><<<gemm_grid, 256>>>(kvc, wv, bv, (float*)gvt);

    cudaFuncSetAttribute(attn_f16, cudaFuncAttributeMaxDynamicSharedMemorySize,
                         ATTN_SMEM_BYTES);
    attn_f16<<<dim3(SL / 128, NB * NH), 256, ATTN_SMEM_BYTES>>>(gq, gk, gvt, gctx);

    gemm_f16<1><<<gemm_grid, 256>>>(gctx, wo, bo, out);
}

// round 5
// speedup vs baseline: 6.1471x; 1.0013x over previous
#include <cuda_runtime.h>
#include <cuda_fp16.h>

#define Eq 1024
#define NH 16
#define DH 64
#define NB 4
#define SL 2048

// Scratch (__device__ globals; alloc-free rule). All fp16 packed as u32 pairs.
__device__ unsigned g_qc[NB * SL * Eq / 2];      // fp16(query)
__device__ unsigned g_kvc[NB * SL * Eq / 2];     // fp16(key_value)
__device__ unsigned g_wq[Eq * Eq / 2], g_wk[Eq * Eq / 2];
__device__ unsigned g_wv[Eq * Eq / 2], g_wo[Eq * Eq / 2];
__device__ unsigned g_q[NB * NH * SL * DH / 2];  // [B,H,S,HD] fp16
__device__ unsigned g_k[NB * NH * SL * DH / 2];  // [B,H,S,HD] fp16
__device__ unsigned g_vt[NB * NH * SL * DH / 2]; // [B,H,HD,S] fp16 (transposed!)
__device__ unsigned g_ctx[NB * SL * Eq / 2];     // [B,S,E] fp16

__device__ __forceinline__ unsigned pkh2(float a, float b) {
    __half2 h = __floats2half2_rn(a, b);
    return *(unsigned*)&h;
}

__device__ __forceinline__ void mma16(float* c, const unsigned* a, const unsigned* b) {
    asm volatile(
        "mma.sync.aligned.m16n8k16.row.col.f32.f16.f16.f32 "
        "{%0,%1,%2,%3}, {%4,%5,%6,%7}, {%8,%9}, {%0,%1,%2,%3};"
        : "+f"(c[0]), "+f"(c[1]), "+f"(c[2]), "+f"(c[3])
        : "r"(a[0]), "r"(a[1]), "r"(a[2]), "r"(a[3]), "r"(b[0]), "r"(b[1]));
}

__device__ __forceinline__ void cp16(unsigned smem_u32, const void* gptr) {
    asm volatile("cp.async.cg.shared.global [%0], [%1], 16;" :: "r"(smem_u32), "l"(gptr));
}
#define CP_COMMIT() asm volatile("cp.async.commit_group;")
#define CP_WAIT0()  asm volatile("cp.async.wait_group 0;")

// ---------------------------------------------------------------------------
// fp32 -> fp16-packed converter
// ---------------------------------------------------------------------------
__global__ void cvt_f16(const float4* __restrict__ src, uint2* __restrict__ dst, int n4) {
    for (int i = blockIdx.x * blockDim.x + threadIdx.x; i < n4; i += gridDim.x * blockDim.x) {
        float4 s = src[i];
        dst[i] = make_uint2(pkh2(s.x, s.y), pkh2(s.z, s.w));
    }
}

// ---------------------------------------------------------------------------
// fp16 GEMM: out = A @ W^T + bias. A,W fp16-packed u32, K-major (512 u32/row).
// 128x128x32 tile, 256 thr (8 warps 4x2), warp 32x64. cp.async 2-stage.
// MODE 0: [B,H,S,HD] fp16; MODE 1: flat fp32; MODE 2: [B,H,HD,S] fp16 transposed.
// ---------------------------------------------------------------------------
#define GP 20  // u32 pitch per row (16 used)

template <int MODE>
__global__ __launch_bounds__(256, 2) void gemm_f16(
    const unsigned* __restrict__ A, const unsigned* __restrict__ W,
    const float* __restrict__ bias, float* __restrict__ out)
{
    __shared__ unsigned As[2][128 * GP];
    __shared__ unsigned Bs[2][128 * GP];

    const int tid = threadIdx.x;
    const int m0 = blockIdx.y * 128, n0 = blockIdx.x * 128;
    const int w = tid >> 5, lane = tid & 31;
    const int wm = w >> 1, wn = w & 1;
    const int g = lane >> 2, q4 = lane & 3;

    // copy mapping: per stage per operand 512 chunks (128 rows x 4x16B)
    const int r0 = tid >> 2, r1 = r0 + 64;
    const int kq = (tid & 3) * 4;

    const unsigned sA = (unsigned)__cvta_generic_to_shared(&As[0][0]);
    const unsigned sB = (unsigned)__cvta_generic_to_shared(&Bs[0][0]);
    const unsigned stageBytes = 128 * GP * 4;

    float acc[2][8][4];
#pragma unroll
    for (int i = 0; i < 2; i++)
#pragma unroll
        for (int j = 0; j < 8; j++)
#pragma unroll
            for (int l = 0; l < 4; l++) acc[i][j][l] = 0.0f;

    auto issue = [&](int t) {
        const int s = t & 1;
        const int kb = t * 16 + kq;  // u32 col in gmem row
        cp16(sA + s * stageBytes + (r0 * GP + kq) * 4, A + (size_t)(m0 + r0) * 512 + kb);
        cp16(sA + s * stageBytes + (r1 * GP + kq) * 4, A + (size_t)(m0 + r1) * 512 + kb);
        cp16(sB + s * stageBytes + (r0 * GP + kq) * 4, W + (size_t)(n0 + r0) * 512 + kb);
        cp16(sB + s * stageBytes + (r1 * GP + kq) * 4, W + (size_t)(n0 + r1) * 512 + kb);
        CP_COMMIT();
    };

    issue(0);
    for (int t = 0; t < 32; t++) {
        CP_WAIT0();
        __syncthreads();
        if (t < 31) issue(t + 1);
        const unsigned* as = &As[t & 1][0];
        const unsigned* bs = &Bs[t & 1][0];
#pragma unroll
        for (int kb4 = 0; kb4 < 16; kb4 += 8) {  // two k16 blocks
            unsigned af[2][4], bf[8][2];
#pragma unroll
            for (int im = 0; im < 2; im++) {
                const int mr = wm * 32 + im * 16 + g;
                af[im][0] = as[mr * GP + kb4 + q4];
                af[im][1] = as[(mr + 8) * GP + kb4 + q4];
                af[im][2] = as[mr * GP + kb4 + q4 + 4];
                af[im][3] = as[(mr + 8) * GP + kb4 + q4 + 4];
            }
#pragma unroll
            for (int jn = 0; jn < 8; jn++) {
                const int nc = wn * 64 + jn * 8 + g;
                bf[jn][0] = bs[nc * GP + kb4 + q4];
                bf[jn][1] = bs[nc * GP + kb4 + q4 + 4];
            }
#pragma unroll
            for (int im = 0; im < 2; im++)
#pragma unroll
                for (int jn = 0; jn < 8; jn++)
                    mma16(acc[im][jn], af[im], bf[jn]);
        }
    }

#pragma unroll
    for (int im = 0; im < 2; im++) {
#pragma unroll
        for (int jn = 0; jn < 8; jn++) {
            const int gn = n0 + wn * 64 + jn * 8 + 2 * q4;
            const float2 bv = *(const float2*)(bias + gn);
#pragma unroll
            for (int h2 = 0; h2 < 2; h2++) {
                const int gm = m0 + wm * 32 + im * 16 + h2 * 8 + g;
                const float o0 = acc[im][jn][2 * h2] + bv.x;
                const float o1 = acc[im][jn][2 * h2 + 1] + bv.y;
                const int bb = gm >> 11, ss = gm & 2047;
                const int hh = gn >> 6, dd = gn & 63;
                if (MODE == 0) {
                    ((unsigned*)out)[(((size_t)(bb * NH + hh)) * SL + ss) * 32 + (dd >> 1)] =
                        pkh2(o0, o1);
                } else if (MODE == 2) {
                    __half* vt = (__half*)out;
                    vt[(((size_t)(bb * NH + hh)) * DH + dd) * SL + ss] = __float2half_rn(o0);
                    vt[(((size_t)(bb * NH + hh)) * DH + dd + 1) * SL + ss] = __float2half_rn(o1);
                } else {
                    *(float2*)(out + (size_t)gm * Eq + gn) = make_float2(o0, o1);
                }
            }
        }
    }
}

// ---------------------------------------------------------------------------
// Fused stablemax attention, fp16 m16n8k16, register-resident T (FA2 identity),
// register denominators, V^T gmem layout, cp.async double-buffered K/V.
// 8 warps x 16 q-rows, full n=64 per warp. One __syncthreads per kv tile.
// ---------------------------------------------------------------------------
#define AP 36  // u32 pitch for 64-half rows (32 used)
#define ATTN_SMEM_BYTES ((128 * AP + 4 * 64 * AP) * 4)

__global__ __launch_bounds__(256, 2) void attn_f16(
    const unsigned* __restrict__ qg, const unsigned* __restrict__ kg,
    const unsigned* __restrict__ vtg, unsigned* __restrict__ ctx)
{
    extern __shared__ unsigned sm[];
    unsigned* Qs = sm;                // [128][AP]
    unsigned* Ks = Qs + 128 * AP;     // [2][64][AP]
    unsigned* Vs = Ks + 2 * 64 * AP;  // [2][64][AP]  rows = dv, cols = kv halfs

    const int tid = threadIdx.x;
    const int wm = tid >> 5, lane = tid & 31;
    const int g = lane >> 2, q4 = lane & 3;
    const int bh = blockIdx.y, q0 = blockIdx.x * 128;
    const int r_lo = wm * 16 + g, r_hi = r_lo + 8;

    const unsigned* qb = qg + ((size_t)bh * SL + q0) * 32;
    const unsigned* kb = kg + (size_t)bh * SL * 32;
    const unsigned* vtb = vtg + (size_t)bh * DH * (SL / 2);  // [64 rows][1024 u32]

    const unsigned sQ = (unsigned)__cvta_generic_to_shared(Qs);
    const unsigned sK = (unsigned)__cvta_generic_to_shared(Ks);
    const unsigned sV = (unsigned)__cvta_generic_to_shared(Vs);
    const unsigned kvStage = 64 * AP * 4;

    auto issue_kv = [&](int t) {
        const int s = t & 1;
        const int kv0 = t * 64;
#pragma unroll
        for (int i = 0; i < 2; i++) {
            const int idx = tid + i * 256;  // 0..511
            const int row = idx >> 3, c = (idx & 7) * 4;
            cp16(sK + s * kvStage + (row * AP + c) * 4, kb + (size_t)(kv0 + row) * 32 + c);
            cp16(sV + s * kvStage + (row * AP + c) * 4, vtb + (size_t)row * 1024 + (kv0 >> 1) + c);
        }
        CP_COMMIT();
    };

    // Prologue: Q tile + first K/V
#pragma unroll
    for (int i = 0; i < 4; i++) {
        const int idx = tid + i * 256;  // 0..1023
        const int row = idx >> 3, c = (idx & 7) * 4;
        cp16(sQ + (row * AP + c) * 4, qb + (size_t)row * 32 + c);
    }
    issue_kv(0);
    CP_WAIT0();
    __syncthreads();

    float oacc[8][4];
#pragma unroll
    for (int j = 0; j < 8; j++)
#pragma unroll
        for (int l = 0; l < 4; l++) oacc[j][l] = 0.0f;
    float dlo = 0.0f, dhi = 0.0f;

    // Q fragments are tile-invariant: hoist
    unsigned qf[4][4];
#pragma unroll
    for (int kb4 = 0; kb4 < 4; kb4++) {
        qf[kb4][0] = Qs[r_lo * AP + kb4 * 8 + q4];
        qf[kb4][1] = Qs[r_hi * AP + kb4 * 8 + q4];
        qf[kb4][2] = Qs[r_lo * AP + kb4 * 8 + q4 + 4];
        qf[kb4][3] = Qs[r_hi * AP + kb4 * 8 + q4 + 4];
    }

    for (int t = 0; t < 32; t++) {
        const unsigned* ks_ = Ks + (t & 1) * 64 * AP;
        const unsigned* vs_ = Vs + (t & 1) * 64 * AP;
        if (t < 31) issue_kv(t + 1);

        // GEMM1: S(16m x 64n) = Q K^T, k = 64 (4 k16 blocks)
        float sacc[8][4];
#pragma unroll
        for (int j = 0; j < 8; j++)
#pragma unroll
            for (int l = 0; l < 4; l++) sacc[j][l] = 0.0f;

#pragma unroll
        for (int kb4 = 0; kb4 < 4; kb4++) {
#pragma unroll
            for (int jn = 0; jn < 8; jn++) {
                const int nc = jn * 8 + g;
                unsigned bf[2];
                bf[0] = ks_[nc * AP + kb4 * 8 + q4];
                bf[1] = ks_[nc * AP + kb4 * 8 + q4 + 4];
                mma16(sacc[jn], qf[kb4], bf);
            }
        }

        // Stablemax numerator -> registers (packed as GEMM2 A-fragments)
        unsigned ta[8], tb[8];
#pragma unroll
        for (int jn = 0; jn < 8; jn++) {
            const float s0 = sacc[jn][0] * 0.125f;
            const float s1 = sacc[jn][1] * 0.125f;
            const float s2 = sacc[jn][2] * 0.125f;
            const float s3 = sacc[jn][3] * 0.125f;
            const float t0 = (s0 >= 0.0f) ? (s0 + 1.0f) : __fdividef(1.0f, 1.0f - s0);
            const float t1 = (s1 >= 0.0f) ? (s1 + 1.0f) : __fdividef(1.0f, 1.0f - s1);
            const float t2 = (s2 >= 0.0f) ? (s2 + 1.0f) : __fdividef(1.0f, 1.0f - s2);
            const float t3 = (s3 >= 0.0f) ? (s3 + 1.0f) : __fdividef(1.0f, 1.0f - s3);
            dlo += t0 + t1;
            dhi += t2 + t3;
            ta[jn] = pkh2(t0, t1);
            tb[jn] = pkh2(t2, t3);
        }

        // GEMM2: O(16m x 64dv) += T V, k = 64; A straight from registers
#pragma unroll
        for (int kb = 0; kb < 4; kb++) {
            unsigned af[4] = {ta[2 * kb], tb[2 * kb], ta[2 * kb + 1], tb[2 * kb + 1]};
#pragma unroll
            for (int jd = 0; jd < 8; jd++) {
                const int dv = jd * 8 + g;
                unsigned bf[2];
                bf[0] = vs_[dv * AP + kb * 8 + q4];
                bf[1] = vs_[dv * AP + kb * 8 + q4 + 4];
                mma16(oacc[jd], af, bf);
            }
        }

        CP_WAIT0();       // next K/V landed
        __syncthreads();  // everyone done reading buffer t&1
    }

    // Row denominators: quad all-reduce (4 lanes share each row)
#pragma unroll
    for (int off = 1; off < 4; off <<= 1) {
        dlo += __shfl_xor_sync(0xffffffffu, dlo, off);
        dhi += __shfl_xor_sync(0xffffffffu, dhi, off);
    }
    const float inv_lo = 1.0f / dlo, inv_hi = 1.0f / dhi;

    // Write ctx fp16 [B,S,E]
    const int b = bh >> 4, h = bh & 15;
    const size_t base_lo = ((size_t)b * SL + q0 + r_lo) * 512 + h * 32;
    const size_t base_hi = ((size_t)b * SL + q0 + r_hi) * 512 + h * 32;
#pragma unroll
    for (int jd = 0; jd < 8; jd++) {
        ctx[base_lo + jd * 4 + q4] = pkh2(oacc[jd][0] * inv_lo, oacc[jd][1] * inv_lo);
        ctx[base_hi + jd * 4 + q4] = pkh2(oacc[jd][2] * inv_hi, oacc[jd][3] * inv_hi);
    }
}

// ---------------------------------------------------------------------------
extern "C" void kernel_launch(void* const* d_in, const int* in_sizes, int n_in,
                              void* d_out, int out_size)
{
    const float* query     = (const float*)d_in[0];
    const float* key_value = (const float*)d_in[1];
    const float* Wq = (const float*)d_in[2];
    const float* bq = (const float*)d_in[3];
    const float* Wk = (const float*)d_in[4];
    const float* bk = (const float*)d_in[5];
    const float* Wv = (const float*)d_in[6];
    const float* bv = (const float*)d_in[7];
    const float* Wo = (const float*)d_in[8];
    const float* bo = (const float*)d_in[9];
    float* out = (float*)d_out;

    unsigned *qc, *kvc, *wq, *wk, *wv, *wo, *gq, *gk, *gvt, *gctx;
    cudaGetSymbolAddress((void**)&qc,  g_qc);
    cudaGetSymbolAddress((void**)&kvc, g_kvc);
    cudaGetSymbolAddress((void**)&wq,  g_wq);
    cudaGetSymbolAddress((void**)&wk,  g_wk);
    cudaGetSymbolAddress((void**)&wv,  g_wv);
    cudaGetSymbolAddress((void**)&wo,  g_wo);
    cudaGetSymbolAddress((void**)&gq,  g_q);
    cudaGetSymbolAddress((void**)&gk,  g_k);
    cudaGetSymbolAddress((void**)&gvt, g_vt);
    cudaGetSymbolAddress((void**)&gctx, g_ctx);

    const int nBig4 = NB * SL * Eq / 4, nW4 = Eq * Eq / 4;
    cvt_f16<<<2048, 256>>>((const float4*)query,     (uint2*)qc,  nBig4);
    cvt_f16<<<2048, 256>>>((const float4*)key_value, (uint2*)kvc, nBig4);
    cvt_f16<<<1024, 256>>>((const float4*)Wq, (uint2*)wq, nW4);
    cvt_f16<<<1024, 256>>>((const float4*)Wk, (uint2*)wk, nW4);
    cvt_f16<<<1024, 256>>>((const float4*)Wv, (uint2*)wv, nW4);
    cvt_f16<<<1024, 256>>>((const float4*)Wo, (uint2*)wo, nW4);

    const dim3 gemm_grid(Eq / 128, (NB * SL) / 128);  // (8, 64)
    gemm_f16<0><<<gemm_grid, 256>>>(qc,  wq, bq, (float*)gq);
    gemm_f16<0><<<gemm_grid, 256>>>(kvc, wk, bk, (float*)gk);
    gemm_f16<2><<<gemm_grid, 256>>>(kvc, wv, bv, (float*)gvt);

    cudaFuncSetAttribute(attn_f16, cudaFuncAttributeMaxDynamicSharedMemorySize,
                         ATTN_SMEM_BYTES);
    attn_f16<<<dim3(SL / 128, NB * NH), 256, ATTN_SMEM_BYTES>>>(gq, gk, gvt, gctx);

    gemm_f16<1><<<gemm_grid, 256>>>(gctx, wo, bo, out);
}